// round 5
// baseline (speedup 1.0000x reference)
#include <cuda_runtime.h>
#include <cuda_fp16.h>

#define BB   2
#define NC   6
#define CCH  256
#define FHH  28
#define FWW  50
#define HWF  (FHH*FWW)      // 1400
#define PP   40000
#define ZZ   3
#define NR   (ZZ*NC)        // 18 records per (b,p)

// u_norm = u * (fW/IMG_W) / (fW-1) * 2 - 1
__device__ __constant__ float CU2 = (float)((50.0/1600.0)/49.0*2.0);
__device__ __constant__ float CV2 = (float)((28.0/900.0)/27.0*2.0);

// Scratch (zero-initialized device globals; no allocations anywhere)
__device__ __half  g_featC[(size_t)BB*NC*HWF*CCH + 64*CCH]; // fp16 conv-ed features + OOB pad (stays 0)
__device__ float   g_wt[CCH*CCH];                           // W transposed: wt[c][o]
__device__ int     g_idx[NR*BB*PP];                         // corner base index or -1
__device__ float4  g_w[NR*BB*PP];                           // 4 bilinear weights (pre-scaled by invc/3)

// ---------------------------------------------------------------------------
// Kernel 1: transpose conv_w (o,c) -> wt (c,o)
// ---------------------------------------------------------------------------
__global__ void transpose_w(const float* __restrict__ w)
{
    int t = blockIdx.x * 256 + threadIdx.x;   // 65536 threads
    int c = t >> 8, o = t & 255;
    g_wt[c*CCH + o] = w[o*CCH + c];
}

// ---------------------------------------------------------------------------
// Kernel 2: per-(b,n) GEMM: featC[hw][o] = sum_c feats[c][hw] * W[o][c]
// BM=128 (hw), BN=64 (o), BK=16, 256 threads, 8x4 micro-tile, double-buffered
// smem. fp32 math, fp16 store (sampling reads fp16).
// ---------------------------------------------------------------------------
__global__ __launch_bounds__(256) void conv_gemm(const float* __restrict__ feats)
{
    const int bn = blockIdx.z;
    const int m0 = blockIdx.x * 128;
    const int n0 = blockIdx.y * 64;
    const float* A = feats + (size_t)bn * CCH * HWF;
    __half* D = g_featC + (size_t)bn * HWF * CCH;

    __shared__ float As[2][16][128];
    __shared__ float Bs[2][16][64];

    const int tid = threadIdx.x;
    const int tm = tid & 15;       // 16 m-groups of 8
    const int tn = tid >> 4;       // 16 n-groups of 4

    float acc[8][4];
#pragma unroll
    for (int i = 0; i < 8; i++)
#pragma unroll
        for (int j = 0; j < 4; j++) acc[i][j] = 0.f;

    // prologue: load tile k0=0 into buffer 0
#pragma unroll
    for (int pass = 0; pass < 8; pass++) {
        int e = tid + 256 * pass;
        int k = e >> 7, m = e & 127;
        int gm = m0 + m;
        As[0][k][m] = (gm < HWF) ? A[(size_t)k * HWF + gm] : 0.f;
    }
#pragma unroll
    for (int pass = 0; pass < 4; pass++) {
        int e = tid + 256 * pass;
        int k = e >> 6, nn = e & 63;
        Bs[0][k][nn] = g_wt[k * CCH + n0 + nn];
    }
    __syncthreads();

    int buf = 0;
    for (int k0 = 0; k0 < CCH; k0 += 16) {
        // prefetch next tile into the other buffer
        if (k0 + 16 < CCH) {
#pragma unroll
            for (int pass = 0; pass < 8; pass++) {
                int e = tid + 256 * pass;
                int k = e >> 7, m = e & 127;
                int gm = m0 + m;
                As[buf^1][k][m] = (gm < HWF) ? A[(size_t)(k0 + 16 + k) * HWF + gm] : 0.f;
            }
#pragma unroll
            for (int pass = 0; pass < 4; pass++) {
                int e = tid + 256 * pass;
                int k = e >> 6, nn = e & 63;
                Bs[buf^1][k][nn] = g_wt[(k0 + 16 + k) * CCH + n0 + nn];
            }
        }
#pragma unroll
        for (int kk = 0; kk < 16; kk++) {
            float4 a0 = *(const float4*)&As[buf][kk][tm * 8];
            float4 a1 = *(const float4*)&As[buf][kk][tm * 8 + 4];
            float4 bv = *(const float4*)&Bs[buf][kk][tn * 4];
            float av[8] = {a0.x, a0.y, a0.z, a0.w, a1.x, a1.y, a1.z, a1.w};
            float bw[4] = {bv.x, bv.y, bv.z, bv.w};
#pragma unroll
            for (int i = 0; i < 8; i++)
#pragma unroll
                for (int j = 0; j < 4; j++)
                    acc[i][j] = fmaf(av[i], bw[j], acc[i][j]);
        }
        __syncthreads();
        buf ^= 1;
    }

#pragma unroll
    for (int i = 0; i < 8; i++) {
        int m = m0 + tm * 8 + i;
        if (m < HWF) {
            __half2 h0 = __floats2half2_rn(acc[i][0], acc[i][1]);
            __half2 h1 = __floats2half2_rn(acc[i][2], acc[i][3]);
            uint2 u;
            u.x = *(unsigned int*)&h0;
            u.y = *(unsigned int*)&h1;
            *(uint2*)&D[(size_t)m * CCH + n0 + tn * 4] = u;
        }
    }
}

// ---------------------------------------------------------------------------
// Kernel 3: projection. One thread per (b,z,p). Buffers the 6 camera records,
// then scales weights by 1/(count+1e-6)/3 so sampling is a flat weighted sum.
// ---------------------------------------------------------------------------
__global__ __launch_bounds__(256) void proj_kernel(const float* __restrict__ intr,
                                                   const float* __restrict__ extr,
                                                   const float* __restrict__ pts)
{
    int t = blockIdx.x * blockDim.x + threadIdx.x;
    if (t >= BB * ZZ * PP) return;
    int p  = t % PP;
    int zb = t / PP;
    int z  = zb % ZZ;
    int b  = zb / ZZ;

    const float* q = pts + ((size_t)z * PP + p) * 3;
    float px = q[0], py = q[1], pz = q[2];
    float cnt = 0.f;

    int    ibuf[NC];
    float4 wbuf[NC];

#pragma unroll
    for (int n = 0; n < NC; n++) {
        const float* E  = extr + (b * NC + n) * 16;
        const float* Kc = intr + (b * NC + n) * 9;
        // E_inv = [R^T | -R^T t]  (rigid transform)
        float Xc = px*E[0] + py*E[4] + pz*E[8]  - (E[0]*E[3] + E[4]*E[7] + E[8]*E[11]);
        float Yc = px*E[1] + py*E[5] + pz*E[9]  - (E[1]*E[3] + E[5]*E[7] + E[9]*E[11]);
        float Zc = px*E[2] + py*E[6] + pz*E[10] - (E[2]*E[3] + E[6]*E[7] + E[10]*E[11]);
        float fx = Kc[0], cx = Kc[2], fy = Kc[4], cy = Kc[5];
        float inv = 1.f / (Zc + 1e-6f);
        float un = (fx * Xc + cx * Zc) * inv * CU2 - 1.f;
        float vn = (fy * Yc + cy * Zc) * inv * CV2 - 1.f;
        bool valid = (Zc > 0.1f) && (un >= -1.f) && (un <= 1.f) && (vn >= -1.f) && (vn <= 1.f);

        int idx = -1;
        float4 w = make_float4(0.f, 0.f, 0.f, 0.f);
        if (valid) {
            float x = (un + 1.f) * 0.5f * (float)(FWW - 1);
            float y = (vn + 1.f) * 0.5f * (float)(FHH - 1);
            float x0f = floorf(x), y0f = floorf(y);
            float wx1 = x - x0f, wy1 = y - y0f;
            float wx0 = 1.f - wx1, wy0 = 1.f - wy1;
            int x0 = (int)x0f, y0 = (int)y0f;
            w = make_float4(wx0 * wy0, wx1 * wy0, wx0 * wy1, wx1 * wy1);
            if (x0 >= FWW - 1) { w.y = 0.f; w.w = 0.f; }  // x1 out of range, weight 0
            if (y0 >= FHH - 1) { w.z = 0.f; w.w = 0.f; }
            idx = y0 * FWW + x0;
            cnt += 1.f;
        }
        ibuf[n] = idx;
        wbuf[n] = w;
    }

    float icc = (1.f / (cnt + 1e-6f)) * (1.f / 3.f);
#pragma unroll
    for (int n = 0; n < NC; n++) {
        int rp = ((z * NC + n) * BB + b) * PP + p;
        float4 w = wbuf[n];
        w.x *= icc; w.y *= icc; w.z *= icc; w.w *= icc;
        g_idx[rp] = ibuf[n];
        g_w[rp]   = w;
    }
}

// ---------------------------------------------------------------------------
// Kernel 4: fp16 sampling + BN/ReLU epilogue + coalesced transposed output.
// 256 threads = 8 warps (one pixel-sublane each) x 32 channel-groups of 8.
// Smem transpose row stride = 258 words; stores use a per-lane permutation of
// channel order so every STS.32 round hits 32 distinct banks; read-out with
// stride 258 is even/odd-bank split between og groups -> conflict-free.
// ---------------------------------------------------------------------------
#define SROW 258

__device__ __forceinline__ void accum8(float* a, const uint4& q, float w)
{
    const __half2* h = (const __half2*)&q;
#pragma unroll
    for (int j = 0; j < 4; j++) {
        float2 f = __half22float2(h[j]);
        a[2*j]   = fmaf(f.x, w, a[2*j]);
        a[2*j+1] = fmaf(f.y, w, a[2*j+1]);
    }
}

__global__ __launch_bounds__(256, 3) void sample_kernel(const float* __restrict__ convb,
                                                        const float* __restrict__ gamma,
                                                        const float* __restrict__ beta,
                                                        const float* __restrict__ mean,
                                                        const float* __restrict__ var,
                                                        float* __restrict__ out)
{
    __shared__ float so[16 * SROW];

    const int b   = blockIdx.y;
    const int p0  = blockIdx.x * 32;
    const int tid = threadIdx.x;
    const int cg  = tid & 31;     // channel group (8 channels)
    const int ps  = tid >> 5;     // warp id = pixel sub-lane 0..7
    const int o0  = cg * 8;
    const int jrot = (cg + (cg >> 3)) & 7;  // store-order rotation (bank perm)

    // BN + conv bias epilogue constants (per 8 channels)
    float sc[8], bi[8];
#pragma unroll
    for (int j = 0; j < 8; j++) {
        float s = gamma[o0 + j] * rsqrtf(var[o0 + j] + 1e-5f);
        sc[j] = s;
        bi[j] = (convb[o0 + j] - mean[o0 + j]) * s + beta[o0 + j];
    }

    const uint4* fc = (const uint4*)g_featC;
    const size_t ob = (size_t)b * CCH * PP + p0;

#pragma unroll 1
    for (int chunk = 0; chunk < 2; chunk++) {
#pragma unroll 1
        for (int i = 0; i < 2; i++) {
            const int lp = i * 8 + ps;            // local pixel 0..15
            const int p  = p0 + chunk * 16 + lp;

            // Preload all 18 corner indices (independent warp-uniform loads)
            int idxs[NR];
#pragma unroll
            for (int r = 0; r < NR; r++)
                idxs[r] = g_idx[(r * BB + b) * PP + p];

            float a[8];
#pragma unroll
            for (int j = 0; j < 8; j++) a[j] = 0.f;

#pragma unroll
            for (int z = 0; z < ZZ; z++) {
#pragma unroll
                for (int n = 0; n < NC; n++) {
                    const int r = z * NC + n;
                    const int idx = idxs[r];
                    if (idx >= 0) {
                        float4 w = g_w[(r * BB + b) * PP + p];
                        const uint4* f = fc + ((size_t)(b * NC + n) * HWF + idx) * 32 + cg;
                        uint4 q00 = f[0];
                        uint4 q01 = f[32];
                        uint4 q10 = f[FWW * 32];
                        uint4 q11 = f[(FWW + 1) * 32];
                        accum8(a, q00, w.x);
                        accum8(a, q01, w.y);
                        accum8(a, q10, w.z);
                        accum8(a, q11, w.w);
                    }
                }
            }
            // Conflict-free transpose stores: lane cg writes its 8 channels in
            // rotated order; address = canonical channel slot (readout unchanged).
            const int row = lp * SROW + o0;
#pragma unroll
            for (int jj = 0; jj < 8; jj++) {
                int j = (jj + jrot) & 7;
                so[row + j] = fmaxf(fmaf(a[j], sc[j], bi[j]), 0.f);
            }
        }
        __syncthreads();

        // Transposed write-out: 16 consecutive threads write 16 consecutive
        // pixels of one o-row (64B coalesced stores).
        const int px = tid & 15;
        const int og = tid >> 4;          // 0..15
#pragma unroll
        for (int ot = 0; ot < 16; ot++) {
            int o = og + ot * 16;
            out[ob + (size_t)o * PP + chunk * 16 + px] = so[px * SROW + o];
        }
        __syncthreads();
    }
}

// ---------------------------------------------------------------------------
extern "C" void kernel_launch(void* const* d_in, const int* in_sizes, int n_in,
                              void* d_out, int out_size)
{
    const float* feats = (const float*)d_in[0];
    const float* intr  = (const float*)d_in[1];
    const float* extr  = (const float*)d_in[2];
    const float* pts   = (const float*)d_in[3];
    const float* convw = (const float*)d_in[4];
    const float* convb = (const float*)d_in[5];
    const float* gamma = (const float*)d_in[6];
    const float* beta  = (const float*)d_in[7];
    const float* mean  = (const float*)d_in[8];
    const float* var   = (const float*)d_in[9];
    float* out = (float*)d_out;

    transpose_w<<<256, 256>>>(convw);
    conv_gemm<<<dim3(11, 4, BB * NC), 256>>>(feats);
    proj_kernel<<<(BB * ZZ * PP + 255) / 256, 256>>>(intr, extr, pts);
    sample_kernel<<<dim3(PP / 32, BB), 256>>>(convb, gamma, beta, mean, var, out);
}

// round 6
// speedup vs baseline: 1.7478x; 1.7478x over previous
#include <cuda_runtime.h>
#include <cuda_fp16.h>
#include <cstdint>

#define BB   2
#define NC   6
#define CCH  256
#define FHH  28
#define FWW  50
#define HWF  (FHH*FWW)      // 1400
#define HWP  1408           // padded M for HMMA (22 * 64)
#define PP   40000
#define ZZ   3
#define NR   (ZZ*NC)        // 18 records per (b,p)

// u_norm = u * (fW/IMG_W) / (fW-1) * 2 - 1
__device__ __constant__ float CU2 = (float)((50.0/1600.0)/49.0*2.0);
__device__ __constant__ float CV2 = (float)((28.0/900.0)/27.0*2.0);

// Scratch (zero-initialized device globals; no allocations anywhere)
__device__ __half  g_featC[(size_t)BB*NC*HWF*CCH + 64*CCH]; // fp16 conv-ed features + OOB pad (stays 0)
__device__ __half  g_featH[(size_t)BB*NC*HWP*CCH];          // fp16 feats transposed [bn][hw][c], rows>=1400 zero
__device__ __half  g_whT[CCH*CCH];                          // fp16 W transposed: whT[c][o]
__device__ int     g_idx[NR*BB*PP];                         // corner base index or -1
__device__ float4  g_w[NR*BB*PP];                           // 4 bilinear weights (pre-scaled by invc/3)

// ---------------------------------------------------------------------------
// Kernel 1a: W (o,c) fp32 -> whT (c,o) fp16
// ---------------------------------------------------------------------------
__global__ void prep_w(const float* __restrict__ w)
{
    int t = blockIdx.x * 256 + threadIdx.x;   // 65536 threads
    int c = t >> 8, o = t & 255;
    g_whT[c*CCH + o] = __float2half(w[o*CCH + c]);
}

// ---------------------------------------------------------------------------
// Kernel 1b: feats [bn][c][hw] fp32 -> g_featH [bn][hw][c] fp16 (32x32 tiles)
// ---------------------------------------------------------------------------
__global__ void prep_feats(const float* __restrict__ feats)
{
    __shared__ float t[32][33];
    const int bn  = blockIdx.z;
    const int hw0 = blockIdx.x * 32;
    const int c0  = blockIdx.y * 32;
    const int tx  = threadIdx.x, ty = threadIdx.y;   // 32 x 8

    const float* src = feats + (size_t)bn * CCH * HWF;
#pragma unroll
    for (int r = 0; r < 4; r++) {
        int c  = c0 + ty + r * 8;
        int hw = hw0 + tx;
        t[ty + r*8][tx] = (hw < HWF) ? src[(size_t)c * HWF + hw] : 0.f;
    }
    __syncthreads();
    __half* dst = g_featH + (size_t)bn * HWP * CCH;
#pragma unroll
    for (int r = 0; r < 4; r++) {
        int i  = ty + r * 8;                 // local hw
        int hw = hw0 + i;                    // < 1408 always
        dst[(size_t)hw * CCH + c0 + tx] = __float2half(t[tx][i]);
    }
}

// ---------------------------------------------------------------------------
// Kernel 2: HMMA GEMM per (b,n): featC[hw][o] = sum_c featH[hw][c] * W[o][c]
// BM=64, BN=256, BK=16; 8 warps = 2(m) x 4(n); warp tile m32 n64.
// mma.sync.m16n8k16 f16 x f16 -> f32. Double-buffered smem, padded strides
// (A row 24 halves, B row 264 halves) for conflict-free ldmatrix.
// ---------------------------------------------------------------------------
#define GBM 64
#define GBK 16
#define ASTR 24
#define BSTR 264

__device__ __forceinline__ uint32_t smem_u32(const void* p)
{
    return (uint32_t)__cvta_generic_to_shared(p);
}

__device__ __forceinline__ void ldm_x4(uint32_t* r, uint32_t addr)
{
    asm volatile("ldmatrix.sync.aligned.m8n8.x4.shared.b16 {%0,%1,%2,%3}, [%4];"
                 : "=r"(r[0]), "=r"(r[1]), "=r"(r[2]), "=r"(r[3]) : "r"(addr));
}
__device__ __forceinline__ void ldm_x4t(uint32_t* r, uint32_t addr)
{
    asm volatile("ldmatrix.sync.aligned.m8n8.x4.trans.shared.b16 {%0,%1,%2,%3}, [%4];"
                 : "=r"(r[0]), "=r"(r[1]), "=r"(r[2]), "=r"(r[3]) : "r"(addr));
}
__device__ __forceinline__ void mma16816(float* d, const uint32_t* a, const uint32_t* b)
{
    asm volatile("mma.sync.aligned.m16n8k16.row.col.f32.f16.f16.f32 "
                 "{%0,%1,%2,%3}, {%4,%5,%6,%7}, {%8,%9}, {%0,%1,%2,%3};"
                 : "+f"(d[0]), "+f"(d[1]), "+f"(d[2]), "+f"(d[3])
                 : "r"(a[0]), "r"(a[1]), "r"(a[2]), "r"(a[3]), "r"(b[0]), "r"(b[1]));
}

__global__ __launch_bounds__(256) void conv_hmma()
{
    const int bn = blockIdx.y;              // 0..11
    const int m0 = blockIdx.x * GBM;

    __shared__ __half As[2][GBM * ASTR];
    __shared__ __half Bs[2][GBK * BSTR];

    const int tid  = threadIdx.x;
    const int lane = tid & 31;
    const int wid  = tid >> 5;
    const int wm   = wid >> 2;              // 0..1
    const int wn   = wid & 3;               // 0..3

    const __half* A = g_featH + (size_t)bn * HWP * CCH;

    float acc[2][8][4];
#pragma unroll
    for (int i = 0; i < 2; i++)
#pragma unroll
        for (int j = 0; j < 8; j++)
#pragma unroll
            for (int q = 0; q < 4; q++) acc[i][j][q] = 0.f;

    // tile-load lambda targets
    const int ar = tid >> 1;                // A row (t<128)
    const int ah = (tid & 1) * 8;           // A half-offset

    // prologue: tile k0=0 -> buf 0
    if (tid < 128) {
        uint4 v = *(const uint4*)&A[(size_t)(m0 + ar) * CCH + ah];
        *(uint4*)&As[0][ar * ASTR + ah] = v;
    }
#pragma unroll
    for (int s = 0; s < 2; s++) {
        int v = tid + 256 * s;              // 0..511
        int row = v >> 5, c = v & 31;
        uint4 u = *(const uint4*)&g_whT[(size_t)row * CCH + c * 8];
        *(uint4*)&Bs[0][row * BSTR + c * 8] = u;
    }
    __syncthreads();

    int buf = 0;
    for (int kt = 0; kt < CCH / GBK; kt++) {
        // prefetch next tile into registers (overlaps with mma below)
        uint4 pa;  uint4 pb[2];
        const bool more = (kt + 1 < CCH / GBK);
        if (more) {
            int k0 = (kt + 1) * GBK;
            if (tid < 128)
                pa = *(const uint4*)&A[(size_t)(m0 + ar) * CCH + k0 + ah];
#pragma unroll
            for (int s = 0; s < 2; s++) {
                int v = tid + 256 * s;
                int row = v >> 5, c = v & 31;
                pb[s] = *(const uint4*)&g_whT[(size_t)(k0 + row) * CCH + c * 8];
            }
        }

        // fragments from buf
        uint32_t af[2][4];
#pragma unroll
        for (int i = 0; i < 2; i++) {
            uint32_t addr = smem_u32(&As[buf][(wm*32 + i*16 + (lane & 15)) * ASTR + (lane >> 4) * 8]);
            ldm_x4(af[i], addr);
        }
        uint32_t bf[8][2];
#pragma unroll
        for (int j4 = 0; j4 < 4; j4++) {
            uint32_t r[4];
            uint32_t addr = smem_u32(&Bs[buf][(((lane >> 3) & 1) * 8 + (lane & 7)) * BSTR
                                              + wn*64 + j4*16 + (lane >> 4) * 8]);
            ldm_x4t(r, addr);
            bf[2*j4][0]   = r[0]; bf[2*j4][1]   = r[1];
            bf[2*j4+1][0] = r[2]; bf[2*j4+1][1] = r[3];
        }
#pragma unroll
        for (int i = 0; i < 2; i++)
#pragma unroll
            for (int j = 0; j < 8; j++)
                mma16816(acc[i][j], af[i], bf[j]);

        if (more) {
            if (tid < 128)
                *(uint4*)&As[buf ^ 1][ar * ASTR + ah] = pa;
#pragma unroll
            for (int s = 0; s < 2; s++) {
                int v = tid + 256 * s;
                int row = v >> 5, c = v & 31;
                *(uint4*)&Bs[buf ^ 1][row * BSTR + c * 8] = pb[s];
            }
        }
        __syncthreads();
        buf ^= 1;
    }

    // epilogue: fp16 store into g_featC[bn][hw][o]
    __half* D = g_featC + (size_t)bn * HWF * CCH;
    const int gid = lane >> 2;              // 0..7
    const int tig = lane & 3;               // 0..3
#pragma unroll
    for (int i = 0; i < 2; i++) {
        int r0 = m0 + wm*32 + i*16 + gid;
#pragma unroll
        for (int j = 0; j < 8; j++) {
            int col = wn*64 + j*8 + tig*2;
            if (r0 < HWF) {
                __half2 h = __floats2half2_rn(acc[i][j][0], acc[i][j][1]);
                *(__half2*)&D[(size_t)r0 * CCH + col] = h;
            }
            if (r0 + 8 < HWF) {
                __half2 h = __floats2half2_rn(acc[i][j][2], acc[i][j][3]);
                *(__half2*)&D[(size_t)(r0 + 8) * CCH + col] = h;
            }
        }
    }
}

// ---------------------------------------------------------------------------
// Kernel 3: projection. One thread per (b,z,p). Buffers the 6 camera records,
// then scales weights by 1/(count+1e-6)/3 so sampling is a flat weighted sum.
// ---------------------------------------------------------------------------
__global__ __launch_bounds__(256) void proj_kernel(const float* __restrict__ intr,
                                                   const float* __restrict__ extr,
                                                   const float* __restrict__ pts)
{
    int t = blockIdx.x * blockDim.x + threadIdx.x;
    if (t >= BB * ZZ * PP) return;
    int p  = t % PP;
    int zb = t / PP;
    int z  = zb % ZZ;
    int b  = zb / ZZ;

    const float* q = pts + ((size_t)z * PP + p) * 3;
    float px = q[0], py = q[1], pz = q[2];
    float cnt = 0.f;

    int    ibuf[NC];
    float4 wbuf[NC];

#pragma unroll
    for (int n = 0; n < NC; n++) {
        const float* E  = extr + (b * NC + n) * 16;
        const float* Kc = intr + (b * NC + n) * 9;
        // E_inv = [R^T | -R^T t]  (rigid transform)
        float Xc = px*E[0] + py*E[4] + pz*E[8]  - (E[0]*E[3] + E[4]*E[7] + E[8]*E[11]);
        float Yc = px*E[1] + py*E[5] + pz*E[9]  - (E[1]*E[3] + E[5]*E[7] + E[9]*E[11]);
        float Zc = px*E[2] + py*E[6] + pz*E[10] - (E[2]*E[3] + E[6]*E[7] + E[10]*E[11]);
        float fx = Kc[0], cx = Kc[2], fy = Kc[4], cy = Kc[5];
        float inv = 1.f / (Zc + 1e-6f);
        float un = (fx * Xc + cx * Zc) * inv * CU2 - 1.f;
        float vn = (fy * Yc + cy * Zc) * inv * CV2 - 1.f;
        bool valid = (Zc > 0.1f) && (un >= -1.f) && (un <= 1.f) && (vn >= -1.f) && (vn <= 1.f);

        int idx = -1;
        float4 w = make_float4(0.f, 0.f, 0.f, 0.f);
        if (valid) {
            float x = (un + 1.f) * 0.5f * (float)(FWW - 1);
            float y = (vn + 1.f) * 0.5f * (float)(FHH - 1);
            float x0f = floorf(x), y0f = floorf(y);
            float wx1 = x - x0f, wy1 = y - y0f;
            float wx0 = 1.f - wx1, wy0 = 1.f - wy1;
            int x0 = (int)x0f, y0 = (int)y0f;
            w = make_float4(wx0 * wy0, wx1 * wy0, wx0 * wy1, wx1 * wy1);
            if (x0 >= FWW - 1) { w.y = 0.f; w.w = 0.f; }  // x1 out of range, weight 0
            if (y0 >= FHH - 1) { w.z = 0.f; w.w = 0.f; }
            idx = y0 * FWW + x0;
            cnt += 1.f;
        }
        ibuf[n] = idx;
        wbuf[n] = w;
    }

    float icc = (1.f / (cnt + 1e-6f)) * (1.f / 3.f);
#pragma unroll
    for (int n = 0; n < NC; n++) {
        int rp = ((z * NC + n) * BB + b) * PP + p;
        float4 w = wbuf[n];
        w.x *= icc; w.y *= icc; w.z *= icc; w.w *= icc;
        g_idx[rp] = ibuf[n];
        g_w[rp]   = w;
    }
}

// ---------------------------------------------------------------------------
// Kernel 4: fp16 sampling + BN/ReLU epilogue + coalesced transposed output.
// (exact R4 configuration — best measured sampler variant for fp16 features)
// ---------------------------------------------------------------------------
__device__ __forceinline__ void accum8(float* a, const uint4& q, float w)
{
    const __half2* h = (const __half2*)&q;
#pragma unroll
    for (int j = 0; j < 4; j++) {
        float2 f = __half22float2(h[j]);
        a[2*j]   = fmaf(f.x, w, a[2*j]);
        a[2*j+1] = fmaf(f.y, w, a[2*j+1]);
    }
}

__global__ __launch_bounds__(256, 3) void sample_kernel(const float* __restrict__ convb,
                                                        const float* __restrict__ gamma,
                                                        const float* __restrict__ beta,
                                                        const float* __restrict__ mean,
                                                        const float* __restrict__ var,
                                                        float* __restrict__ out)
{
    __shared__ float so[16 * 257];

    const int b   = blockIdx.y;
    const int p0  = blockIdx.x * 32;
    const int tid = threadIdx.x;
    const int cg  = tid & 31;     // channel group (8 channels)
    const int ps  = tid >> 5;     // warp id = pixel sub-lane 0..7
    const int o0  = cg * 8;

    // BN + conv bias epilogue constants (per 8 channels)
    float sc[8], bi[8];
#pragma unroll
    for (int j = 0; j < 8; j++) {
        float s = gamma[o0 + j] * rsqrtf(var[o0 + j] + 1e-5f);
        sc[j] = s;
        bi[j] = (convb[o0 + j] - mean[o0 + j]) * s + beta[o0 + j];
    }

    const uint4* fc = (const uint4*)g_featC;
    const size_t ob = (size_t)b * CCH * PP + p0;

#pragma unroll 1
    for (int chunk = 0; chunk < 2; chunk++) {
#pragma unroll 1
        for (int i = 0; i < 2; i++) {
            const int lp = i * 8 + ps;            // local pixel 0..15
            const int p  = p0 + chunk * 16 + lp;

            // Preload all 18 corner indices (independent warp-uniform loads)
            int idxs[NR];
#pragma unroll
            for (int r = 0; r < NR; r++)
                idxs[r] = g_idx[(r * BB + b) * PP + p];

            float a[8];
#pragma unroll
            for (int j = 0; j < 8; j++) a[j] = 0.f;

#pragma unroll
            for (int z = 0; z < ZZ; z++) {
#pragma unroll
                for (int n = 0; n < NC; n++) {
                    const int r = z * NC + n;
                    const int idx = idxs[r];
                    if (idx >= 0) {
                        float4 w = g_w[(r * BB + b) * PP + p];
                        const uint4* f = fc + ((size_t)(b * NC + n) * HWF + idx) * 32 + cg;
                        uint4 q00 = f[0];
                        uint4 q01 = f[32];
                        uint4 q10 = f[FWW * 32];
                        uint4 q11 = f[(FWW + 1) * 32];
                        accum8(a, q00, w.x);
                        accum8(a, q01, w.y);
                        accum8(a, q10, w.z);
                        accum8(a, q11, w.w);
                    }
                }
            }
            int row = lp * 257 + o0;
#pragma unroll
            for (int j = 0; j < 8; j++)
                so[row + j] = fmaxf(fmaf(a[j], sc[j], bi[j]), 0.f);
        }
        __syncthreads();

        // Transposed write-out: 16 consecutive threads write 16 consecutive
        // pixels of one o-row (64B coalesced stores).
        const int px = tid & 15;
        const int og = tid >> 4;          // 0..15
#pragma unroll
        for (int ot = 0; ot < 16; ot++) {
            int o = og + ot * 16;
            out[ob + (size_t)o * PP + chunk * 16 + px] = so[px * 257 + o];
        }
        __syncthreads();
    }
}

// ---------------------------------------------------------------------------
extern "C" void kernel_launch(void* const* d_in, const int* in_sizes, int n_in,
                              void* d_out, int out_size)
{
    const float* feats = (const float*)d_in[0];
    const float* intr  = (const float*)d_in[1];
    const float* extr  = (const float*)d_in[2];
    const float* pts   = (const float*)d_in[3];
    const float* convw = (const float*)d_in[4];
    const float* convb = (const float*)d_in[5];
    const float* gamma = (const float*)d_in[6];
    const float* beta  = (const float*)d_in[7];
    const float* mean  = (const float*)d_in[8];
    const float* var   = (const float*)d_in[9];
    float* out = (float*)d_out;

    prep_w<<<256, 256>>>(convw);
    prep_feats<<<dim3(HWP/32, CCH/32, BB*NC), dim3(32, 8)>>>(feats);
    conv_hmma<<<dim3(HWP/GBM, BB*NC), 256>>>();
    proj_kernel<<<(BB * ZZ * PP + 255) / 256, 256>>>(intr, extr, pts);
    sample_kernel<<<dim3(PP / 32, BB), 256>>>(convb, gamma, beta, mean, var, out);
}